// round 11
// baseline (speedup 1.0000x reference)
#include <cuda_runtime.h>
#include <cuda_fp16.h>
#include <math.h>
#include <stdint.h>

// ---------------- Problem constants ----------------
#define BB 16
#define SS 256
#define HH 768
#define LL 12
#define AH 12
#define DH 64
#define FF 3072
#define NL 9
#define NT (BB*SS)           // 4096 tokens
#define NBH (BB*AH)          // 192 batch*head
#define QKVN (3*HH)          // 2304

typedef long long ll;

// ---------------- Device scratch (static, allocation-free) ----------------
__device__ float g_x   [NT*HH];
__device__ float g_qkv [NT*QKVN];
__device__ float g_ctx [NT*HH];
__device__ float g_tmp [NT*HH];
__device__ float g_h   [NT*FF];
__device__ float g_sc  [(ll)NBH*SS*SS];
__device__ float g_vo  [NT*HH];
__device__ float g_bqkv[LL*QKVN];

// packed (transposed, fp16 hi/lo) weights: [L][N][K]
__device__ __half g_qkvw_h[(ll)LL*QKVN*HH];
__device__ __half g_qkvw_l[(ll)LL*QKVN*HH];
__device__ __half g_ow_h  [(ll)LL*HH*HH];
__device__ __half g_ow_l  [(ll)LL*HH*HH];
__device__ __half g_f1w_h [(ll)LL*FF*HH];
__device__ __half g_f1w_l [(ll)LL*FF*HH];
__device__ __half g_f2w_h [(ll)LL*HH*FF];
__device__ __half g_f2w_l [(ll)LL*HH*FF];
// transposed V per layer: [bh][d][s] fp16 hi/lo
__device__ __half g_vt_h  [(ll)NBH*DH*SS];
__device__ __half g_vt_l  [(ll)NBH*DH*SS];

// ---------------- PTX helpers ----------------
__device__ __forceinline__ void ldmx4(uint32_t r[4], uint32_t addr) {
    asm volatile("ldmatrix.sync.aligned.m8n8.x4.shared.b16 {%0,%1,%2,%3}, [%4];"
        : "=r"(r[0]), "=r"(r[1]), "=r"(r[2]), "=r"(r[3]) : "r"(addr));
}

__device__ __forceinline__ void mma16(float c[4], const uint32_t a[4], const uint32_t b[2]) {
    asm volatile(
        "mma.sync.aligned.m16n8k16.row.col.f32.f16.f16.f32 "
        "{%0,%1,%2,%3}, {%4,%5,%6,%7}, {%8,%9}, {%0,%1,%2,%3};"
        : "+f"(c[0]), "+f"(c[1]), "+f"(c[2]), "+f"(c[3])
        : "r"(a[0]), "r"(a[1]), "r"(a[2]), "r"(a[3]), "r"(b[0]), "r"(b[1]));
}

__device__ __forceinline__ void cpa16(uint32_t dst, const void* src) {
    asm volatile("cp.async.ca.shared.global [%0], [%1], 16;" :: "r"(dst), "l"(src));
}
__device__ __forceinline__ void cpa_commit() { asm volatile("cp.async.commit_group;"); }
__device__ __forceinline__ void cpa_wait1()  { asm volatile("cp.async.wait_group 1;"); }
__device__ __forceinline__ void cpa_wait0()  { asm volatile("cp.async.wait_group 0;"); }

// split fp32 pair -> fp16 hi pair (packed) + fp16 lo pair (packed)
__device__ __forceinline__ void split2(float x, float y, uint32_t& hp, uint32_t& lp) {
    __half hx = __float2half_rn(x), hy = __float2half_rn(y);
    __half lx = __float2half_rn(x - __half2float(hx));
    __half ly = __float2half_rn(y - __half2float(hy));
    hp = (uint32_t)__half_as_ushort(hx) | ((uint32_t)__half_as_ushort(hy) << 16);
    lp = (uint32_t)__half_as_ushort(lx) | ((uint32_t)__half_as_ushort(ly) << 16);
}

// ================= fp16 3-term tensor-core GEMM =================
// C[z] = act( A[z] @ B[z]^T (+bias) ).  A: f32 [M,K] (lda).
// B (logical [N,K]):  BPACK=1 -> pre-split fp16 hi/lo arrays (ldb = packed row len);
//                     BPACK=0 -> f32 [N,K] (ldb), converted in prefetch.
// BM=128, BN=64, BK=64, 256 threads (8 warps 2x4), warp tile 64x16.
// 2 CTAs/SM (acc=32 regs, smem 108KB): cross-CTA overlap hides sync windows.
// smem/stage 55296B (pitch 144B = 64 halves + pad):
//   Ah@0 (18432), Al@18432, Bh@36864 (9216), Bl@46080.
#define HG_STAGE 55296
#define HG_SMEM  (2*HG_STAGE)

template<int BPACK, int ACT>
__global__ void __launch_bounds__(256, 2)
hgemm(const float* __restrict__ A, const float* __restrict__ Bf,
      const __half* __restrict__ Bph, const __half* __restrict__ Bpl,
      const float* __restrict__ bias, float* __restrict__ C,
      int M, int N, int K, int lda, int ldb, int ldc,
      int divA, ll sA1, ll sA2,
      int divB, ll sB1, ll sB2,
      int divC, ll sC1, ll sC2)
{
    extern __shared__ char sm[];
    const int tid = threadIdx.x;
    const int lane = tid & 31;
    const int wid = tid >> 5;
    const int wm = wid & 1;        // 2 warps in M (64 rows each)
    const int wn = wid >> 1;       // 4 warps in N (16 cols each)
    const int z = blockIdx.z;
    const int tm0 = blockIdx.y * 128;
    const int tn0 = blockIdx.x * 64;

    const float* Ab = A + (ll)(z / divA) * sA1 + (ll)(z % divA) * sA2 + (ll)tm0 * lda;
    const float* Bb = nullptr;
    const __half *Wh = nullptr, *Wl = nullptr;
    if (BPACK) {
        Wh = Bph + (ll)(z / divB) * sB1 + (ll)(z % divB) * sB2;
        Wl = Bpl + (ll)(z / divB) * sB1 + (ll)(z % divB) * sB2;
    } else {
        Bb = Bf + (ll)(z / divB) * sB1 + (ll)(z % divB) * sB2;
    }
    float* Cb = C + (ll)(z / divC) * sC1 + (ll)(z % divC) * sC2;

    uint32_t sbase = (uint32_t)__cvta_generic_to_shared(sm);

    float acc[8][4];
    #pragma unroll
    for (int i = 0; i < 8; i++)
        #pragma unroll
        for (int q = 0; q < 4; q++) acc[i][q] = 0.f;

    auto prefetch = [&](int kt, int s) {
        char* stc = sm + s * HG_STAGE;
        // ---- A: 128 rows x 64 k f32 -> fp16 hi/lo smem (8 float4 per thread) ----
        const float* As0 = Ab + kt * 64;
        #pragma unroll
        for (int j = 0; j < 8; j++) {
            int c = tid + j * 256;             // 0..2047
            int row = c >> 4, kq = c & 15;     // 16 float4 per row
            float4 v = *(const float4*)(As0 + (ll)row * lda + kq * 4);
            uint2 hv, lv;
            split2(v.x, v.y, hv.x, lv.x);
            split2(v.z, v.w, hv.y, lv.y);
            int off = row * 144 + kq * 8;
            *(uint2*)(stc + off) = hv;
            *(uint2*)(stc + 18432 + off) = lv;
        }
        if (BPACK) {
            // ---- B: 64 rows x 64 k fp16 hi/lo via cp.async (4 chunks/thread) ----
            uint32_t std = sbase + s * HG_STAGE + 36864;
            #pragma unroll
            for (int j = 0; j < 4; j++) {
                int c = tid + j * 256;         // 0..1023
                int sel = c >> 9;              // 0 = hi, 1 = lo
                int cc = c & 511;
                int row = cc >> 3, kc = cc & 7;  // 8 x 16B chunks per row
                int n = tn0 + row;
                const __half* src = (sel ? Wl : Wh) + (ll)n * ldb + kt * 64 + kc * 8;
                cpa16(std + sel * 9216 + row * 144 + kc * 16, src);
            }
            cpa_commit();
        } else {
            // ---- B: 64 rows x 64 k f32 -> fp16 hi/lo smem (4 float4 per thread) ----
            char* stb = stc + 36864;
            #pragma unroll
            for (int j = 0; j < 4; j++) {
                int c = tid + j * 256;         // 0..1023
                int row = c >> 4, kq = c & 15;
                int n = tn0 + row;
                float4 v = *(const float4*)(Bb + (ll)n * ldb + kt * 64 + kq * 4);
                uint2 hv, lv;
                split2(v.x, v.y, hv.x, lv.x);
                split2(v.z, v.w, hv.y, lv.y);
                int off = row * 144 + kq * 8;
                *(uint2*)(stb + off) = hv;
                *(uint2*)(stb + 9216 + off) = lv;
            }
        }
    };

    const int KT = K / 64;
    prefetch(0, 0);

    // per-lane ldmatrix address components
    const int arb = (lane & 7) + ((lane >> 3) & 1) * 8;   // A row within 16
    const int akh = (lane >> 4) * 16;                     // A k-half bytes
    const int bq  = lane >> 3;
    const int bnb = ((bq >> 1) << 3) + (lane & 7);        // B n within 16
    const int bkh = (bq & 1) * 16;                        // B k-half bytes

    for (int kt = 0; kt < KT; kt++) {
        const int s = kt & 1;
        if (kt + 1 < KT) { prefetch(kt + 1, s ^ 1); if (BPACK) cpa_wait1(); }
        else             { if (BPACK) cpa_wait0(); }
        __syncthreads();

        uint32_t stA = sbase + s * HG_STAGE;
        uint32_t stB = stA + 36864;

        #pragma unroll
        for (int ks = 0; ks < 4; ks++) {
            // ---- pass 1: hi x hi ----
            uint32_t ah[4][4], bh[2][2];
            #pragma unroll
            for (int mt = 0; mt < 4; mt++) {
                uint32_t ad = stA + (wm * 64 + mt * 16 + arb) * 144 + ks * 32 + akh;
                ldmx4(ah[mt], ad);
            }
            {
                uint32_t bd = stB + (wn * 16 + bnb) * 144 + ks * 32 + bkh;
                uint32_t r[4];
                ldmx4(r, bd);
                bh[0][0] = r[0]; bh[0][1] = r[1]; bh[1][0] = r[2]; bh[1][1] = r[3];
            }
            #pragma unroll
            for (int mt = 0; mt < 4; mt++)
                #pragma unroll
                for (int nt = 0; nt < 2; nt++) mma16(acc[mt*2+nt], ah[mt], bh[nt]);

            // ---- pass 2: lo x hi (load al, reuse bh) ----
            {
                uint32_t al[4][4];
                #pragma unroll
                for (int mt = 0; mt < 4; mt++) {
                    uint32_t ad = stA + 18432 + (wm * 64 + mt * 16 + arb) * 144 + ks * 32 + akh;
                    ldmx4(al[mt], ad);
                }
                #pragma unroll
                for (int mt = 0; mt < 4; mt++)
                    #pragma unroll
                    for (int nt = 0; nt < 2; nt++) mma16(acc[mt*2+nt], al[mt], bh[nt]);
            }

            // ---- pass 3: hi x lo (load bl, reuse ah) ----
            {
                uint32_t bl[2][2];
                uint32_t bd = stB + 9216 + (wn * 16 + bnb) * 144 + ks * 32 + bkh;
                uint32_t r[4];
                ldmx4(r, bd);
                bl[0][0] = r[0]; bl[0][1] = r[1]; bl[1][0] = r[2]; bl[1][1] = r[3];
                #pragma unroll
                for (int mt = 0; mt < 4; mt++)
                    #pragma unroll
                    for (int nt = 0; nt < 2; nt++) mma16(acc[mt*2+nt], ah[mt], bl[nt]);
            }
        }
        __syncthreads();
    }

    // ---- epilogue ----
    #pragma unroll
    for (int mt = 0; mt < 4; mt++) {
        int r0 = tm0 + wm * 64 + mt * 16 + (lane >> 2);
        #pragma unroll
        for (int nt = 0; nt < 2; nt++) {
            int col = tn0 + wn * 16 + nt * 8 + 2 * (lane & 3);
            float v0 = acc[mt*2+nt][0], v1 = acc[mt*2+nt][1];
            float v2 = acc[mt*2+nt][2], v3 = acc[mt*2+nt][3];
            if (bias) {
                float2 b2 = *(const float2*)(bias + col);
                v0 += b2.x; v1 += b2.y; v2 += b2.x; v3 += b2.y;
            }
            if (ACT == 1) {
                float t;
                t = v0; v0 = 0.5f*t*(1.f + tanhf(0.7978845608028654f*(t + 0.044715f*t*t*t)));
                t = v1; v1 = 0.5f*t*(1.f + tanhf(0.7978845608028654f*(t + 0.044715f*t*t*t)));
                t = v2; v2 = 0.5f*t*(1.f + tanhf(0.7978845608028654f*(t + 0.044715f*t*t*t)));
                t = v3; v3 = 0.5f*t*(1.f + tanhf(0.7978845608028654f*(t + 0.044715f*t*t*t)));
            }
            *(float2*)&Cb[(ll)r0 * ldc + col]       = make_float2(v0, v1);
            *(float2*)&Cb[(ll)(r0 + 8) * ldc + col] = make_float2(v2, v3);
        }
    }
}

template<int BPACK, int ACT>
static void hgemm_launch(const float* A, const float* Bf, const __half* Wh, const __half* Wl,
                         const float* bias, float* C,
                         int M, int N, int K, int lda, int ldb, int ldc, int batches,
                         int divA, ll sA1, ll sA2,
                         int divB, ll sB1, ll sB2,
                         int divC, ll sC1, ll sC2)
{
    dim3 grid(N / 64, M / 128, batches);
    hgemm<BPACK, ACT><<<grid, 256, HG_SMEM>>>(A, Bf, Wh, Wl, bias, C, M, N, K, lda, ldb, ldc,
                                              divA, sA1, sA2, divB, sB1, sB2, divC, sC1, sC2);
}

// ================= weight packing (transpose + fp16 split) =================
__global__ void pack_w_kernel(const float* __restrict__ W, __half* __restrict__ Ph,
                              __half* __restrict__ Pl, int K, int N)
{
    __shared__ float t[32][33];
    int l = blockIdx.z;
    const float* Wb = W + (ll)l * K * N;
    __half* Phb = Ph + (ll)l * N * K;
    __half* Plb = Pl + (ll)l * N * K;
    int k0 = blockIdx.x * 32, n0 = blockIdx.y * 32;
    int tx = threadIdx.x, ty = threadIdx.y;
    #pragma unroll
    for (int j = 0; j < 4; j++)
        t[ty + j * 8][tx] = Wb[(ll)(k0 + ty + j * 8) * N + n0 + tx];
    __syncthreads();
    #pragma unroll
    for (int j = 0; j < 4; j++) {
        int n = n0 + ty + j * 8, k = k0 + tx;
        float v = t[tx][ty + j * 8];
        __half h = __float2half_rn(v);
        __half lo = __float2half_rn(v - __half2float(h));
        Phb[(ll)n * K + k] = h;
        Plb[(ll)n * K + k] = lo;
    }
}

__global__ void pack_qkvw_kernel(const float* __restrict__ Wq, const float* __restrict__ Wk,
                                 const float* __restrict__ Wv,
                                 __half* __restrict__ Ph, __half* __restrict__ Pl)
{
    __shared__ float t[32][33];
    int l = blockIdx.z;
    int k0 = blockIdx.x * 32, n0 = blockIdx.y * 32;
    int sel = n0 / HH;
    const float* Wb = ((sel == 0) ? Wq : (sel == 1) ? Wk : Wv) + (ll)l * HH * HH;
    int nc0 = n0 - sel * HH;
    __half* Phb = Ph + (ll)l * QKVN * HH;
    __half* Plb = Pl + (ll)l * QKVN * HH;
    int tx = threadIdx.x, ty = threadIdx.y;
    #pragma unroll
    for (int j = 0; j < 4; j++)
        t[ty + j * 8][tx] = Wb[(ll)(k0 + ty + j * 8) * HH + nc0 + tx];
    __syncthreads();
    #pragma unroll
    for (int j = 0; j < 4; j++) {
        int n = n0 + ty + j * 8, k = k0 + tx;
        float v = t[tx][ty + j * 8];
        __half h = __float2half_rn(v);
        __half lo = __float2half_rn(v - __half2float(h));
        Phb[(ll)n * HH + k] = h;
        Plb[(ll)n * HH + k] = lo;
    }
}

__global__ void pack_bias_kernel(const float* __restrict__ bq, const float* __restrict__ bk,
                                 const float* __restrict__ bv, float* __restrict__ bp)
{
    int i = blockIdx.x * 256 + threadIdx.x;
    if (i >= LL * QKVN) return;
    int l = i / QKVN, col = i % QKVN;
    int sel = col / HH, cc = col % HH;
    const float* b = (sel == 0) ? bq : (sel == 1) ? bk : bv;
    bp[i] = b[l * HH + cc];
}

// ---- V transpose + fp16 split: qkv V slice [s][d] -> Vt [bh][d][s] ----
__global__ void vtrans_kernel(const float* __restrict__ qkv,
                              __half* __restrict__ Vh, __half* __restrict__ Vl)
{
    __shared__ float t[32][33];
    int s0 = blockIdx.x * 32;
    int d0 = blockIdx.y * 32;
    int bh = blockIdx.z;
    int b = bh / AH, h = bh % AH;
    const float* src = qkv + (ll)(b * SS) * QKVN + 2 * HH + h * DH;
    int tx = threadIdx.x, ty = threadIdx.y;
    #pragma unroll
    for (int j = 0; j < 4; j++)
        t[ty + j * 8][tx] = src[(ll)(s0 + ty + j * 8) * QKVN + d0 + tx];
    __syncthreads();
    __half* Vhb = Vh + (ll)bh * DH * SS;
    __half* Vlb = Vl + (ll)bh * DH * SS;
    #pragma unroll
    for (int j = 0; j < 4; j++) {
        int d = d0 + ty + j * 8, sidx = s0 + tx;
        float v = t[tx][ty + j * 8];
        __half hh = __float2half_rn(v);
        __half lo = __float2half_rn(v - __half2float(hh));
        Vhb[(ll)d * SS + sidx] = hh;
        Vlb[(ll)d * SS + sidx] = lo;
    }
}

// ================= block reduction =================
template<bool MAXR>
__device__ __forceinline__ float block_reduce(float v) {
    __shared__ float sh[33];
    int lane = threadIdx.x & 31, w = threadIdx.x >> 5;
    #pragma unroll
    for (int o = 16; o; o >>= 1) {
        float t = __shfl_xor_sync(0xffffffffu, v, o);
        v = MAXR ? fmaxf(v, t) : (v + t);
    }
    if (lane == 0) sh[w] = v;
    __syncthreads();
    if (w == 0) {
        int nw = blockDim.x >> 5;
        float t = (lane < nw) ? sh[lane] : (MAXR ? -3.4e38f : 0.f);
        #pragma unroll
        for (int o = 16; o; o >>= 1) {
            float u = __shfl_xor_sync(0xffffffffu, t, o);
            t = MAXR ? fmaxf(t, u) : (t + u);
        }
        if (lane == 0) sh[32] = t;
    }
    __syncthreads();
    float r = sh[32];
    __syncthreads();
    return r;
}

// ================= elementwise kernels =================
__global__ void embed_ln_kernel(const int* __restrict__ ids, const int* __restrict__ types,
                                const float* __restrict__ wemb, const float* __restrict__ pemb,
                                const float* __restrict__ temb,
                                const float* __restrict__ g, const float* __restrict__ b,
                                float* __restrict__ x)
{
    int tok = blockIdx.x;
    int s = tok % SS;
    int t = threadIdx.x;
    int id = ids[tok];
    int ty = types[tok];
    float v[3];
    float sum = 0.f;
    #pragma unroll
    for (int i = 0; i < 3; i++) {
        int h = t + i*256;
        float val = wemb[(ll)id*HH + h] + pemb[s*HH + h] + temb[ty*HH + h];
        v[i] = val; sum += val;
    }
    float mean = block_reduce<false>(sum) * (1.f/HH);
    float sq = 0.f;
    #pragma unroll
    for (int i = 0; i < 3; i++) { float d = v[i] - mean; sq += d*d; }
    float var = block_reduce<false>(sq) * (1.f/HH);
    float rstd = rsqrtf(var + 1e-12f);
    #pragma unroll
    for (int i = 0; i < 3; i++) {
        int h = t + i*256;
        x[(ll)tok*HH + h] = (v[i] - mean) * rstd * g[h] + b[h];
    }
}

__global__ void add_ln_kernel(const float* __restrict__ xin, const float* __restrict__ tmp,
                              const float* __restrict__ g, const float* __restrict__ b,
                              float* __restrict__ xout)
{
    int tok = blockIdx.x;
    int t = threadIdx.x;
    float v[3];
    float sum = 0.f;
    #pragma unroll
    for (int i = 0; i < 3; i++) {
        int h = t + i*256;
        float val = xin[(ll)tok*HH + h] + tmp[(ll)tok*HH + h];
        v[i] = val; sum += val;
    }
    float mean = block_reduce<false>(sum) * (1.f/HH);
    float sq = 0.f;
    #pragma unroll
    for (int i = 0; i < 3; i++) { float d = v[i] - mean; sq += d*d; }
    float var = block_reduce<false>(sq) * (1.f/HH);
    float rstd = rsqrtf(var + 1e-12f);
    #pragma unroll
    for (int i = 0; i < 3; i++) {
        int h = t + i*256;
        xout[(ll)tok*HH + h] = (v[i] - mean) * rstd * g[h] + b[h];
    }
}

__global__ void attn_softmax_kernel(float* __restrict__ sc, const int* __restrict__ mask)
{
    ll row = blockIdx.x;
    int t = threadIdx.x;
    int bh = (int)(row >> 8);
    int b = bh / AH;
    float* p = sc + row * SS;
    float madd = mask[b*SS + t] ? 0.f : -10000.f;
    float v = p[t] * 0.125f + madd;
    float mx = block_reduce<true>(v);
    float e = expf(v - mx);
    float s = block_reduce<false>(e);
    p[t] = e / s;
}

__global__ void compact_kernel(const float* __restrict__ x, const int* __restrict__ valid,
                               float* __restrict__ vo)
{
    int b = blockIdx.x;
    int t = threadIdx.x;
    __shared__ int vload[SS];
    __shared__ int rank[SS];
    vload[t] = valid[b*SS + t];
    __syncthreads();
    int r = 0;
    for (int i = 0; i < t; i++) r += vload[i];
    rank[t] = r;
    __syncthreads();
    float* vob = vo + (ll)b * SS * HH;
    for (int i = t; i < SS*HH; i += 256) vob[i] = 0.f;
    __syncthreads();
    int w = t >> 5, lane = t & 31;
    for (int s = w; s < SS; s += 8) {
        if (vload[s]) {
            const float* src = x + ((ll)b*SS + s) * HH;
            float* dst = vob + (ll)rank[s] * HH;
            for (int i = lane; i < HH; i += 32) dst[i] = src[i];
        }
    }
}

__global__ void cls_kernel(const float* __restrict__ vo, const float* __restrict__ W,
                           const float* __restrict__ bias, float* __restrict__ out)
{
    int tok = blockIdx.x;
    int t = threadIdx.x;
    const float* v = vo + (ll)tok * HH;
    float acc[NL];
    #pragma unroll
    for (int j = 0; j < NL; j++) acc[j] = 0.f;
    for (int i = t; i < HH; i += 256) {
        float xv = v[i];
        const float* w = W + (ll)i * NL;
        #pragma unroll
        for (int j = 0; j < NL; j++) acc[j] += xv * w[j];
    }
    __shared__ float red[NL*256];
    #pragma unroll
    for (int j = 0; j < NL; j++) red[j*256 + t] = acc[j];
    __syncthreads();
    for (int o = 128; o; o >>= 1) {
        if (t < o) {
            #pragma unroll
            for (int j = 0; j < NL; j++) red[j*256 + t] += red[j*256 + t + o];
        }
        __syncthreads();
    }
    if (t == 0) {
        float lg[NL];
        float mx = -3.4e38f;
        #pragma unroll
        for (int j = 0; j < NL; j++) { lg[j] = red[j*256] + bias[j]; mx = fmaxf(mx, lg[j]); }
        float s = 0.f;
        #pragma unroll
        for (int j = 0; j < NL; j++) { lg[j] = expf(lg[j] - mx); s += lg[j]; }
        float inv = 1.f / s;
        #pragma unroll
        for (int j = 0; j < NL; j++) out[(ll)tok*NL + j] = lg[j] * inv;
    }
}

// ================= launch orchestration =================
extern "C" void kernel_launch(void* const* d_in, const int* in_sizes, int n_in,
                              void* d_out, int out_size)
{
    const int*   ids   = (const int*)  d_in[0];
    const int*   imask = (const int*)  d_in[1];
    const int*   types = (const int*)  d_in[2];
    const int*   vmask = (const int*)  d_in[3];
    const float* wemb  = (const float*)d_in[4];
    const float* pemb  = (const float*)d_in[5];
    const float* temb  = (const float*)d_in[6];
    const float* eg    = (const float*)d_in[7];
    const float* eb    = (const float*)d_in[8];
    const float* Wq    = (const float*)d_in[9];
    const float* bq    = (const float*)d_in[10];
    const float* Wk    = (const float*)d_in[11];
    const float* bk    = (const float*)d_in[12];
    const float* Wv    = (const float*)d_in[13];
    const float* bv    = (const float*)d_in[14];
    const float* Wo    = (const float*)d_in[15];
    const float* bo    = (const float*)d_in[16];
    const float* ag    = (const float*)d_in[17];
    const float* ab    = (const float*)d_in[18];
    const float* W1    = (const float*)d_in[19];
    const float* b1    = (const float*)d_in[20];
    const float* W2    = (const float*)d_in[21];
    const float* b2    = (const float*)d_in[22];
    const float* fg    = (const float*)d_in[23];
    const float* fb    = (const float*)d_in[24];
    const float* cW    = (const float*)d_in[25];
    const float* cb    = (const float*)d_in[26];
    float* out = (float*)d_out;

    float *x, *qkv, *ctx, *tmp, *hbuf, *sc, *vo, *bqkv;
    __half *qkvw_h, *qkvw_l, *ow_h, *ow_l, *f1w_h, *f1w_l, *f2w_h, *f2w_l, *vt_h, *vt_l;
    cudaGetSymbolAddress((void**)&x,    g_x);
    cudaGetSymbolAddress((void**)&qkv,  g_qkv);
    cudaGetSymbolAddress((void**)&ctx,  g_ctx);
    cudaGetSymbolAddress((void**)&tmp,  g_tmp);
    cudaGetSymbolAddress((void**)&hbuf, g_h);
    cudaGetSymbolAddress((void**)&sc,   g_sc);
    cudaGetSymbolAddress((void**)&vo,   g_vo);
    cudaGetSymbolAddress((void**)&bqkv, g_bqkv);
    cudaGetSymbolAddress((void**)&qkvw_h, g_qkvw_h);
    cudaGetSymbolAddress((void**)&qkvw_l, g_qkvw_l);
    cudaGetSymbolAddress((void**)&ow_h,   g_ow_h);
    cudaGetSymbolAddress((void**)&ow_l,   g_ow_l);
    cudaGetSymbolAddress((void**)&f1w_h,  g_f1w_h);
    cudaGetSymbolAddress((void**)&f1w_l,  g_f1w_l);
    cudaGetSymbolAddress((void**)&f2w_h,  g_f2w_h);
    cudaGetSymbolAddress((void**)&f2w_l,  g_f2w_l);
    cudaGetSymbolAddress((void**)&vt_h,   g_vt_h);
    cudaGetSymbolAddress((void**)&vt_l,   g_vt_l);

    cudaFuncSetAttribute(hgemm<1,0>, cudaFuncAttributeMaxDynamicSharedMemorySize, HG_SMEM);
    cudaFuncSetAttribute(hgemm<1,1>, cudaFuncAttributeMaxDynamicSharedMemorySize, HG_SMEM);
    cudaFuncSetAttribute(hgemm<0,0>, cudaFuncAttributeMaxDynamicSharedMemorySize, HG_SMEM);

    // 0) pack weights: transpose to [N][K], split fp16 hi/lo
    {
        dim3 blk(32, 8);
        pack_qkvw_kernel<<<dim3(HH/32, QKVN/32, LL), blk>>>(Wq, Wk, Wv, qkvw_h, qkvw_l);
        pack_w_kernel<<<dim3(HH/32, HH/32, LL),  blk>>>(Wo, ow_h,  ow_l,  HH, HH);
        pack_w_kernel<<<dim3(HH/32, FF/32, LL),  blk>>>(W1, f1w_h, f1w_l, HH, FF);
        pack_w_kernel<<<dim3(FF/32, HH/32, LL),  blk>>>(W2, f2w_h, f2w_l, FF, HH);
        pack_bias_kernel<<<(LL*QKVN + 255)/256, 256>>>(bq, bk, bv, bqkv);
    }

    // 1) embeddings + LN
    embed_ln_kernel<<<NT, 256>>>(ids, types, wemb, pemb, temb, eg, eb, x);

    // 2) transformer layers
    for (int l = 0; l < LL; l++) {
        const float* bol = bo + (ll)l*HH;
        const float* b1l = b1 + (ll)l*FF;
        const float* b2l = b2 + (ll)l*HH;
        const float* agl = ag + (ll)l*HH;    const float* abl = ab + (ll)l*HH;
        const float* fgl = fg + (ll)l*HH;    const float* fbl = fb + (ll)l*HH;

        // fused QKV projection
        hgemm_launch<1,0>(x, nullptr, qkvw_h + (ll)l*QKVN*HH, qkvw_l + (ll)l*QKVN*HH,
                          bqkv + (ll)l*QKVN, qkv, NT, QKVN, HH, HH, HH, QKVN, 1,
                          1,0,0, 1,0,0, 1,0,0);

        // V transpose + split
        vtrans_kernel<<<dim3(SS/32, DH/32, NBH), dim3(32, 8)>>>(qkv, vt_h, vt_l);

        // scores = Q * K^T per (b,h):  A = Q view, B = K view (f32 convert path)
        hgemm_launch<0,0>(qkv, qkv + HH, nullptr, nullptr, nullptr, sc,
                          SS, SS, DH, QKVN, QKVN, SS, NBH,
                          AH, (ll)SS*QKVN, DH,
                          AH, (ll)SS*QKVN, DH,
                          1,  (ll)SS*SS, 0);
        attn_softmax_kernel<<<NBH*SS, 256>>>(sc, imask);

        // ctx = P * V per (b,h):  B = pre-transposed V (packed path), N = 64 exact
        hgemm_launch<1,0>(sc, nullptr, vt_h, vt_l, nullptr, ctx,
                          SS, DH, SS, SS, SS, HH, NBH,
                          1,  (ll)SS*SS, 0,
                          1,  (ll)DH*SS, 0,
                          AH, (ll)SS*HH, DH);

        // output projection
        hgemm_launch<1,0>(ctx, nullptr, ow_h + (ll)l*HH*HH, ow_l + (ll)l*HH*HH,
                          bol, tmp, NT, HH, HH, HH, HH, HH, 1,
                          1,0,0, 1,0,0, 1,0,0);
        add_ln_kernel<<<NT, 256>>>(x, tmp, agl, abl, x);

        // FFN
        hgemm_launch<1,1>(x, nullptr, f1w_h + (ll)l*FF*HH, f1w_l + (ll)l*FF*HH,
                          b1l, hbuf, NT, FF, HH, HH, HH, FF, 1,
                          1,0,0, 1,0,0, 1,0,0);
        hgemm_launch<1,0>(hbuf, nullptr, f2w_h + (ll)l*HH*FF, f2w_l + (ll)l*HH*FF,
                          b2l, tmp, NT, HH, FF, FF, FF, HH, 1,
                          1,0,0, 1,0,0, 1,0,0);
        add_ln_kernel<<<NT, 256>>>(x, tmp, fgl, fbl, x);
    }

    // 3) valid-token compaction
    compact_kernel<<<BB, 256>>>(x, vmask, vo);

    // 4) classifier + softmax
    cls_kernel<<<NT, 256>>>(vo, cW, cb, out);

    (void)in_sizes; (void)n_in; (void)out_size;
}

// round 13
// speedup vs baseline: 1.1499x; 1.1499x over previous
#include <cuda_runtime.h>
#include <cuda_fp16.h>
#include <math.h>
#include <stdint.h>

// ---------------- Problem constants ----------------
#define BB 16
#define SS 256
#define HH 768
#define LL 12
#define AH 12
#define DH 64
#define FF 3072
#define NL 9
#define NT (BB*SS)           // 4096 tokens
#define NBH (BB*AH)          // 192 batch*head
#define QKVN (3*HH)          // 2304

typedef long long ll;

// ---------------- Device scratch (static, allocation-free) ----------------
__device__ float g_x   [NT*HH];
__device__ float g_qkv [NT*QKVN];
__device__ float g_ctx [NT*HH];
__device__ float g_tmp [NT*HH];
__device__ float g_h   [NT*FF];
__device__ float g_vo  [NT*HH];
__device__ float g_bqkv[LL*QKVN];

// packed (transposed, fp16 hi/lo) weights: [L][N][K]
__device__ __half g_qkvw_h[(ll)LL*QKVN*HH];
__device__ __half g_qkvw_l[(ll)LL*QKVN*HH];
__device__ __half g_ow_h  [(ll)LL*HH*HH];
__device__ __half g_ow_l  [(ll)LL*HH*HH];
__device__ __half g_f1w_h [(ll)LL*FF*HH];
__device__ __half g_f1w_l [(ll)LL*FF*HH];
__device__ __half g_f2w_h [(ll)LL*HH*FF];
__device__ __half g_f2w_l [(ll)LL*HH*FF];
// transposed V per layer: [bh][d][s] fp16 hi/lo
__device__ __half g_vt_h  [(ll)NBH*DH*SS];
__device__ __half g_vt_l  [(ll)NBH*DH*SS];

// ---------------- PTX helpers ----------------
__device__ __forceinline__ void ldmx4(uint32_t r[4], uint32_t addr) {
    asm volatile("ldmatrix.sync.aligned.m8n8.x4.shared.b16 {%0,%1,%2,%3}, [%4];"
        : "=r"(r[0]), "=r"(r[1]), "=r"(r[2]), "=r"(r[3]) : "r"(addr));
}

__device__ __forceinline__ void mma16(float c[4], const uint32_t a[4], const uint32_t b[2]) {
    asm volatile(
        "mma.sync.aligned.m16n8k16.row.col.f32.f16.f16.f32 "
        "{%0,%1,%2,%3}, {%4,%5,%6,%7}, {%8,%9}, {%0,%1,%2,%3};"
        : "+f"(c[0]), "+f"(c[1]), "+f"(c[2]), "+f"(c[3])
        : "r"(a[0]), "r"(a[1]), "r"(a[2]), "r"(a[3]), "r"(b[0]), "r"(b[1]));
}

__device__ __forceinline__ void cpa16(uint32_t dst, const void* src) {
    asm volatile("cp.async.ca.shared.global [%0], [%1], 16;" :: "r"(dst), "l"(src));
}
__device__ __forceinline__ void cpa16p(uint32_t dst, const void* src, int src_bytes) {
    asm volatile("cp.async.ca.shared.global [%0], [%1], 16, %2;"
                 :: "r"(dst), "l"(src), "r"(src_bytes));
}
__device__ __forceinline__ void cpa_commit() { asm volatile("cp.async.commit_group;"); }
__device__ __forceinline__ void cpa_wait1()  { asm volatile("cp.async.wait_group 1;"); }
__device__ __forceinline__ void cpa_wait0()  { asm volatile("cp.async.wait_group 0;"); }

// split fp32 pair -> fp16 hi pair (packed) + fp16 lo pair (packed)
__device__ __forceinline__ void split2(float x, float y, uint32_t& hp, uint32_t& lp) {
    __half hx = __float2half_rn(x), hy = __float2half_rn(y);
    __half lx = __float2half_rn(x - __half2float(hx));
    __half ly = __float2half_rn(y - __half2float(hy));
    hp = (uint32_t)__half_as_ushort(hx) | ((uint32_t)__half_as_ushort(hy) << 16);
    lp = (uint32_t)__half_as_ushort(lx) | ((uint32_t)__half_as_ushort(ly) << 16);
}

// ================= fp16 3-term tensor-core GEMM (R5-exact, dense only) =================
// C[z] = act( A[z] @ B[z]^T (+bias) ).  A: f32 [M,K] (lda).  B pre-split fp16 hi/lo.
// BM=128, BN=128, BK=32, 256 threads (8 warps 2x4), warp tile 64x32.
#define HG_STAGE 40960
#define HG_SMEM  (2*HG_STAGE)

template<int BPACK, int ACT>
__global__ void __launch_bounds__(256)
hgemm(const float* __restrict__ A, const float* __restrict__ Bf,
      const __half* __restrict__ Bph, const __half* __restrict__ Bpl,
      const float* __restrict__ bias, float* __restrict__ C,
      int M, int N, int K, int lda, int ldb, int ldc,
      int divA, ll sA1, ll sA2,
      int divB, ll sB1, ll sB2,
      int divC, ll sC1, ll sC2)
{
    extern __shared__ char sm[];
    const int tid = threadIdx.x;
    const int lane = tid & 31;
    const int wid = tid >> 5;
    const int wm = wid & 1;
    const int wn = wid >> 1;
    const int z = blockIdx.z;
    const int tm0 = blockIdx.y * 128;
    const int tn0 = blockIdx.x * 128;

    const float* Ab = A + (ll)(z / divA) * sA1 + (ll)(z % divA) * sA2 + (ll)tm0 * lda;
    const float* Bb = nullptr;
    const __half *Wh = nullptr, *Wl = nullptr;
    if (BPACK) {
        Wh = Bph + (ll)(z / divB) * sB1 + (ll)(z % divB) * sB2;
        Wl = Bpl + (ll)(z / divB) * sB1 + (ll)(z % divB) * sB2;
    } else {
        Bb = Bf + (ll)(z / divB) * sB1 + (ll)(z % divB) * sB2;
    }
    float* Cb = C + (ll)(z / divC) * sC1 + (ll)(z % divC) * sC2;

    uint32_t sbase = (uint32_t)__cvta_generic_to_shared(sm);

    float acc[16][4];
    #pragma unroll
    for (int i = 0; i < 16; i++)
        #pragma unroll
        for (int q = 0; q < 4; q++) acc[i][q] = 0.f;

    auto prefetch = [&](int kt, int s) {
        char* stc = sm + s * HG_STAGE;
        const float* As0 = Ab + kt * 32;
        #pragma unroll
        for (int j = 0; j < 4; j++) {
            int c = tid + j * 256;
            int row = c >> 3, kq = c & 7;
            float4 v = *(const float4*)(As0 + (ll)row * lda + kq * 4);
            uint2 hv, lv;
            split2(v.x, v.y, hv.x, lv.x);
            split2(v.z, v.w, hv.y, lv.y);
            int off = row * 80 + kq * 8;
            *(uint2*)(stc + off) = hv;
            *(uint2*)(stc + 10240 + off) = lv;
        }
        if (BPACK) {
            uint32_t std = sbase + s * HG_STAGE + 20480;
            #pragma unroll
            for (int j = 0; j < 2; j++) {
                int c = tid + j * 256;
                int row = c >> 2, kc = c & 3;
                int n = tn0 + row;
                bool ok = n < N;
                const __half* srcH = ok ? (Wh + (ll)n * ldb + kt * 32 + kc * 8) : Wh;
                const __half* srcL = ok ? (Wl + (ll)n * ldb + kt * 32 + kc * 8) : Wl;
                uint32_t d0 = std + row * 80 + kc * 16;
                cpa16p(d0,         srcH, ok ? 16 : 0);
                cpa16p(d0 + 10240, srcL, ok ? 16 : 0);
            }
            cpa_commit();
        } else {
            char* stb = stc + 20480;
            #pragma unroll
            for (int j = 0; j < 4; j++) {
                int c = tid + j * 256;
                int row = c >> 3, kq = c & 7;
                int n = tn0 + row;
                float4 v = (n < N) ? *(const float4*)(Bb + (ll)n * ldb + kt * 32 + kq * 4)
                                   : make_float4(0.f, 0.f, 0.f, 0.f);
                uint2 hv, lv;
                split2(v.x, v.y, hv.x, lv.x);
                split2(v.z, v.w, hv.y, lv.y);
                int off = row * 80 + kq * 8;
                *(uint2*)(stb + off) = hv;
                *(uint2*)(stb + 9216 + 1024 + off) = lv;   // 10240 = lo offset
            }
        }
    };

    const int KT = K / 32;
    prefetch(0, 0);

    const int arb = (lane & 7) + ((lane >> 3) & 1) * 8;
    const int akh = (lane >> 4) * 16;
    const int bq  = lane >> 3;
    const int bnb = ((bq >> 1) << 3) + (lane & 7);
    const int bkh = (bq & 1) * 16;

    for (int kt = 0; kt < KT; kt++) {
        const int s = kt & 1;
        if (kt + 1 < KT) { prefetch(kt + 1, s ^ 1); if (BPACK) cpa_wait1(); }
        else             { if (BPACK) cpa_wait0(); }
        __syncthreads();

        uint32_t stA = sbase + s * HG_STAGE;
        uint32_t stB = stA + 20480;

        #pragma unroll
        for (int ks = 0; ks < 2; ks++) {
            uint32_t ah[4][4], al[4][4], bh[4][2], bl[4][2];
            #pragma unroll
            for (int mt = 0; mt < 4; mt++) {
                uint32_t ad = stA + (wm * 64 + mt * 16 + arb) * 80 + ks * 32 + akh;
                ldmx4(ah[mt], ad);
                ldmx4(al[mt], ad + 10240);
            }
            #pragma unroll
            for (int p = 0; p < 2; p++) {
                uint32_t bd = stB + (wn * 32 + p * 16 + bnb) * 80 + ks * 32 + bkh;
                uint32_t r[4];
                ldmx4(r, bd);
                bh[p*2][0] = r[0]; bh[p*2][1] = r[1]; bh[p*2+1][0] = r[2]; bh[p*2+1][1] = r[3];
                ldmx4(r, bd + 10240);
                bl[p*2][0] = r[0]; bl[p*2][1] = r[1]; bl[p*2+1][0] = r[2]; bl[p*2+1][1] = r[3];
            }
            #pragma unroll
            for (int mt = 0; mt < 4; mt++)
                #pragma unroll
                for (int nt = 0; nt < 4; nt++) mma16(acc[mt*4+nt], ah[mt], bh[nt]);
            #pragma unroll
            for (int mt = 0; mt < 4; mt++)
                #pragma unroll
                for (int nt = 0; nt < 4; nt++) mma16(acc[mt*4+nt], al[mt], bh[nt]);
            #pragma unroll
            for (int mt = 0; mt < 4; mt++)
                #pragma unroll
                for (int nt = 0; nt < 4; nt++) mma16(acc[mt*4+nt], ah[mt], bl[nt]);
        }
        __syncthreads();
    }

    #pragma unroll
    for (int mt = 0; mt < 4; mt++) {
        int r0 = tm0 + wm * 64 + mt * 16 + (lane >> 2);
        #pragma unroll
        for (int nt = 0; nt < 4; nt++) {
            int col = tn0 + wn * 32 + nt * 8 + 2 * (lane & 3);
            if (col < N) {
                float v0 = acc[mt*4+nt][0], v1 = acc[mt*4+nt][1];
                float v2 = acc[mt*4+nt][2], v3 = acc[mt*4+nt][3];
                if (bias) {
                    float2 b2 = *(const float2*)(bias + col);
                    v0 += b2.x; v1 += b2.y; v2 += b2.x; v3 += b2.y;
                }
                if (ACT == 1) {
                    float t;
                    t = v0; v0 = 0.5f*t*(1.f + tanhf(0.7978845608028654f*(t + 0.044715f*t*t*t)));
                    t = v1; v1 = 0.5f*t*(1.f + tanhf(0.7978845608028654f*(t + 0.044715f*t*t*t)));
                    t = v2; v2 = 0.5f*t*(1.f + tanhf(0.7978845608028654f*(t + 0.044715f*t*t*t)));
                    t = v3; v3 = 0.5f*t*(1.f + tanhf(0.7978845608028654f*(t + 0.044715f*t*t*t)));
                }
                *(float2*)&Cb[(ll)r0 * ldc + col]       = make_float2(v0, v1);
                *(float2*)&Cb[(ll)(r0 + 8) * ldc + col] = make_float2(v2, v3);
            }
        }
    }
}

template<int BPACK, int ACT>
static void hgemm_launch(const float* A, const float* Bf, const __half* Wh, const __half* Wl,
                         const float* bias, float* C,
                         int M, int N, int K, int lda, int ldb, int ldc, int batches,
                         int divA, ll sA1, ll sA2,
                         int divB, ll sB1, ll sB2,
                         int divC, ll sC1, ll sC2)
{
    dim3 grid((N + 127) / 128, M / 128, batches);
    hgemm<BPACK, ACT><<<grid, 256, HG_SMEM>>>(A, Bf, Wh, Wl, bias, C, M, N, K, lda, ldb, ldc,
                                              divA, sA1, sA2, divB, sB1, sB2, divC, sC1, sC2);
}

// ================= fused attention kernel =================
// One block per (bh, 128-row Q chunk). 256 threads (8 warps 2x4).
// Phase 1: S = Q@K^T (3-term) -> scale+mask -> row max/sum -> P=exp in smem (hi/lo).
// Phase 2: ctx = P@V^T (3-term) * (1/rowsum).
#define AT_Q_H   0
#define AT_Q_L   18432
#define AT_K_H   36864
#define AT_K_L   73728
#define AT_P_H   0
#define AT_P_L   67584
#define AT_V_H   135168
#define AT_V_L   168960
#define AT_RED   202752
#define AT_MASK  204800
#define AT_SMEM  205824

__global__ void __launch_bounds__(256, 1)
fattn_kernel(const float* __restrict__ qkv, const __half* __restrict__ Vth,
             const __half* __restrict__ Vtl, const int* __restrict__ mask,
             float* __restrict__ ctx)
{
    extern __shared__ char sm[];
    float* smf = (float*)sm;
    uint32_t sb = (uint32_t)__cvta_generic_to_shared(sm);
    const int tid = threadIdx.x;
    const int lane = tid & 31;
    const int wid = tid >> 5;
    const int wm = wid & 1;
    const int wn = wid >> 1;
    const int qc = blockIdx.x;          // 0..1 (Q row chunk)
    const int bh = blockIdx.y;          // 0..191
    const int b = bh / AH, h = bh % AH;

    // ---- early async V^T load (region disjoint from phase-1 working set) ----
    {
        const __half* vh = Vth + (ll)bh * DH * SS;
        const __half* vl = Vtl + (ll)bh * DH * SS;
        #pragma unroll
        for (int j = 0; j < 8; j++) {
            int c = tid + j * 256;       // 0..2047
            int d = c >> 5, kc = c & 31;
            cpa16(sb + AT_V_H + d * 528 + kc * 16, vh + (ll)d * SS + kc * 8);
            cpa16(sb + AT_V_L + d * 528 + kc * 16, vl + (ll)d * SS + kc * 8);
        }
        cpa_commit();
    }

    // ---- mask to floats ----
    smf[AT_MASK / 4 + tid] = mask[b * SS + tid] ? 0.f : -10000.f;

    // ---- load Q (128x64) and K (256x64), split to fp16 hi/lo ----
    const float* Qg = qkv + (ll)(b * SS + qc * 128) * QKVN + h * DH;
    const float* Kg = qkv + (ll)(b * SS) * QKVN + HH + h * DH;
    #pragma unroll
    for (int j = 0; j < 8; j++) {
        int c = tid + j * 256;
        int row = c >> 4, kq = c & 15;
        float4 v = *(const float4*)(Qg + (ll)row * QKVN + kq * 4);
        uint2 hv, lv;
        split2(v.x, v.y, hv.x, lv.x);
        split2(v.z, v.w, hv.y, lv.y);
        int off = row * 144 + kq * 8;
        *(uint2*)(sm + AT_Q_H + off) = hv;
        *(uint2*)(sm + AT_Q_L + off) = lv;
    }
    #pragma unroll
    for (int j = 0; j < 16; j++) {
        int c = tid + j * 256;
        int row = c >> 4, kq = c & 15;
        float4 v = *(const float4*)(Kg + (ll)row * QKVN + kq * 4);
        uint2 hv, lv;
        split2(v.x, v.y, hv.x, lv.x);
        split2(v.z, v.w, hv.y, lv.y);
        int off = row * 144 + kq * 8;
        *(uint2*)(sm + AT_K_H + off) = hv;
        *(uint2*)(sm + AT_K_L + off) = lv;
    }
    __syncthreads();

    const int arb = (lane & 7) + ((lane >> 3) & 1) * 8;
    const int akh = (lane >> 4) * 16;
    const int bq  = lane >> 3;
    const int bnb = ((bq >> 1) << 3) + (lane & 7);
    const int bkh = (bq & 1) * 16;

    // ---- phase 1: S = Q @ K^T (warp tile 64x64), 3-term ----
    float acc[4][8][4];
    #pragma unroll
    for (int mt = 0; mt < 4; mt++)
        #pragma unroll
        for (int nt = 0; nt < 8; nt++)
            #pragma unroll
            for (int q = 0; q < 4; q++) acc[mt][nt][q] = 0.f;

    #pragma unroll
    for (int ks = 0; ks < 4; ks++) {
        uint32_t ah[4][4], bh4[8][2];
        #pragma unroll
        for (int mt = 0; mt < 4; mt++) {
            uint32_t ad = sb + AT_Q_H + (wm * 64 + mt * 16 + arb) * 144 + ks * 32 + akh;
            ldmx4(ah[mt], ad);
        }
        #pragma unroll
        for (int p = 0; p < 4; p++) {
            uint32_t bd = sb + AT_K_H + (wn * 64 + p * 16 + bnb) * 144 + ks * 32 + bkh;
            uint32_t r[4];
            ldmx4(r, bd);
            bh4[p*2][0] = r[0]; bh4[p*2][1] = r[1]; bh4[p*2+1][0] = r[2]; bh4[p*2+1][1] = r[3];
        }
        #pragma unroll
        for (int mt = 0; mt < 4; mt++)
            #pragma unroll
            for (int nt = 0; nt < 8; nt++) mma16(acc[mt][nt], ah[mt], bh4[nt]);
        // lo x hi
        {
            uint32_t al[4][4];
            #pragma unroll
            for (int mt = 0; mt < 4; mt++) {
                uint32_t ad = sb + AT_Q_L + (wm * 64 + mt * 16 + arb) * 144 + ks * 32 + akh;
                ldmx4(al[mt], ad);
            }
            #pragma unroll
            for (int mt = 0; mt < 4; mt++)
                #pragma unroll
                for (int nt = 0; nt < 8; nt++) mma16(acc[mt][nt], al[mt], bh4[nt]);
        }
        // hi x lo
        {
            uint32_t bl[8][2];
            #pragma unroll
            for (int p = 0; p < 4; p++) {
                uint32_t bd = sb + AT_K_L + (wn * 64 + p * 16 + bnb) * 144 + ks * 32 + bkh;
                uint32_t r[4];
                ldmx4(r, bd);
                bl[p*2][0] = r[0]; bl[p*2][1] = r[1]; bl[p*2+1][0] = r[2]; bl[p*2+1][1] = r[3];
            }
            #pragma unroll
            for (int mt = 0; mt < 4; mt++)
                #pragma unroll
                for (int nt = 0; nt < 8; nt++) mma16(acc[mt][nt], ah[mt], bl[nt]);
        }
    }

    // ---- scale + mask + row max (within warp) ----
    const int gid = lane >> 2;
    const int tq2 = 2 * (lane & 3);
    #pragma unroll
    for (int mt = 0; mt < 4; mt++) {
        float vx0 = -3.4e38f, vx1 = -3.4e38f;
        #pragma unroll
        for (int nt = 0; nt < 8; nt++) {
            int col = wn * 64 + nt * 8 + tq2;
            float m0 = smf[AT_MASK / 4 + col];
            float m1 = smf[AT_MASK / 4 + col + 1];
            acc[mt][nt][0] = acc[mt][nt][0] * 0.125f + m0;
            acc[mt][nt][1] = acc[mt][nt][1] * 0.125f + m1;
            acc[mt][nt][2] = acc[mt][nt][2] * 0.125f + m0;
            acc[mt][nt][3] = acc[mt][nt][3] * 0.125f + m1;
            vx0 = fmaxf(vx0, fmaxf(acc[mt][nt][0], acc[mt][nt][1]));
            vx1 = fmaxf(vx1, fmaxf(acc[mt][nt][2], acc[mt][nt][3]));
        }
        vx0 = fmaxf(vx0, __shfl_xor_sync(0xffffffffu, vx0, 1));
        vx0 = fmaxf(vx0, __shfl_xor_sync(0xffffffffu, vx0, 2));
        vx1 = fmaxf(vx1, __shfl_xor_sync(0xffffffffu, vx1, 1));
        vx1 = fmaxf(vx1, __shfl_xor_sync(0xffffffffu, vx1, 2));
        if ((lane & 3) == 0) {
            int r = wm * 64 + mt * 16 + gid;
            smf[AT_RED / 4 + wn * 128 + r]     = vx0;
            smf[AT_RED / 4 + wn * 128 + r + 8] = vx1;
        }
    }
    __syncthreads();

    float gx0[4], gx1[4];
    #pragma unroll
    for (int mt = 0; mt < 4; mt++) {
        int r = wm * 64 + mt * 16 + gid;
        float a0 = smf[AT_RED/4 + r],       a1 = smf[AT_RED/4 + 128 + r];
        float a2 = smf[AT_RED/4 + 256 + r], a3 = smf[AT_RED/4 + 384 + r];
        gx0[mt] = fmaxf(fmaxf(a0, a1), fmaxf(a2, a3));
        a0 = smf[AT_RED/4 + r + 8];       a1 = smf[AT_RED/4 + 128 + r + 8];
        a2 = smf[AT_RED/4 + 256 + r + 8]; a3 = smf[AT_RED/4 + 384 + r + 8];
        gx1[mt] = fmaxf(fmaxf(a0, a1), fmaxf(a2, a3));
    }
    __syncthreads();   // done reading maxes; red reused for sums

    // ---- exp, store P (hi/lo) into smem (overwrites dead Q/K), partial sums ----
    #pragma unroll
    for (int mt = 0; mt < 4; mt++) {
        int r0 = wm * 64 + mt * 16 + gid;
        int r1 = r0 + 8;
        float s0 = 0.f, s1 = 0.f;
        #pragma unroll
        for (int nt = 0; nt < 8; nt++) {
            int col = wn * 64 + nt * 8 + tq2;
            float e0 = expf(acc[mt][nt][0] - gx0[mt]);
            float e1 = expf(acc[mt][nt][1] - gx0[mt]);
            float e2 = expf(acc[mt][nt][2] - gx1[mt]);
            float e3 = expf(acc[mt][nt][3] - gx1[mt]);
            s0 += e0 + e1; s1 += e2 + e3;
            uint32_t hp, lp;
            split2(e0, e1, hp, lp);
            *(uint32_t*)(sm + AT_P_H + r0 * 528 + col * 2) = hp;
            *(uint32_t*)(sm + AT_P_L + r0 * 528 + col * 2) = lp;
            split2(e2, e3, hp, lp);
            *(uint32_t*)(sm + AT_P_H + r1 * 528 + col * 2) = hp;
            *(uint32_t*)(sm + AT_P_L + r1 * 528 + col * 2) = lp;
        }
        s0 += __shfl_xor_sync(0xffffffffu, s0, 1);
        s0 += __shfl_xor_sync(0xffffffffu, s0, 2);
        s1 += __shfl_xor_sync(0xffffffffu, s1, 1);
        s1 += __shfl_xor_sync(0xffffffffu, s1, 2);
        if ((lane & 3) == 0) {
            smf[AT_RED / 4 + wn * 128 + r0] = s0;
            smf[AT_RED / 4 + wn * 128 + r1] = s1;
        }
    }
    cpa_wait0();        // own V chunks done
    __syncthreads();    // all P stores + all V chunks visible; sums in red

    float inv0[4], inv1[4];
    #pragma unroll
    for (int mt = 0; mt < 4; mt++) {
        int r = wm * 64 + mt * 16 + gid;
        float t0 = smf[AT_RED/4 + r] + smf[AT_RED/4 + 128 + r]
                 + smf[AT_RED/4 + 256 + r] + smf[AT_RED/4 + 384 + r];
        float t1 = smf[AT_RED/4 + r + 8] + smf[AT_RED/4 + 128 + r + 8]
                 + smf[AT_RED/4 + 256 + r + 8] + smf[AT_RED/4 + 384 + r + 8];
        inv0[mt] = 1.f / t0;
        inv1[mt] = 1.f / t1;
    }

    // ---- phase 2: ctx = P @ V^T (warp tile 64x16), 3-term, K-dim = 256 ----
    float a2[4][2][4];
    #pragma unroll
    for (int mt = 0; mt < 4; mt++)
        #pragma unroll
        for (int nt = 0; nt < 2; nt++)
            #pragma unroll
            for (int q = 0; q < 4; q++) a2[mt][nt][q] = 0.f;

    #pragma unroll 8
    for (int ks = 0; ks < 16; ks++) {
        uint32_t ah[4][4], bhf[2][2];
        #pragma unroll
        for (int mt = 0; mt < 4; mt++) {
            uint32_t ad = sb + AT_P_H + (wm * 64 + mt * 16 + arb) * 528 + ks * 32 + akh;
            ldmx4(ah[mt], ad);
        }
        {
            uint32_t bd = sb + AT_V_H + (wn * 16 + bnb) * 528 + ks * 32 + bkh;
            uint32_t r[4];
            ldmx4(r, bd);
            bhf[0][0] = r[0]; bhf[0][1] = r[1]; bhf[1][0] = r[2]; bhf[1][1] = r[3];
        }
        #pragma unroll
        for (int mt = 0; mt < 4; mt++)
            #pragma unroll
            for (int nt = 0; nt < 2; nt++) mma16(a2[mt][nt], ah[mt], bhf[nt]);
        {
            uint32_t al[4][4];
            #pragma unroll
            for (int mt = 0; mt < 4; mt++) {
                uint32_t ad = sb + AT_P_L + (wm * 64 + mt * 16 + arb) * 528 + ks * 32 + akh;
                ldmx4(al[mt], ad);
            }
            #pragma unroll
            for (int mt = 0; mt < 4; mt++)
                #pragma unroll
                for (int nt = 0; nt < 2; nt++) mma16(a2[mt][nt], al[mt], bhf[nt]);
        }
        {
            uint32_t blf[2][2];
            uint32_t bd = sb + AT_V_L + (wn * 16 + bnb) * 528 + ks * 32 + bkh;
            uint32_t r[4];
            ldmx4(r, bd);
            blf[0][0] = r[0]; blf[0][1] = r[1]; blf[1][0] = r[2]; blf[1][1] = r[3];
            #pragma unroll
            for (int mt = 0; mt < 4; mt++)
                #pragma unroll
                for (int nt = 0; nt < 2; nt++) mma16(a2[mt][nt], ah[mt], blf[nt]);
        }
    }

    // ---- epilogue: normalize and write ctx ----
    float* Cb = ctx + (ll)(b * SS + qc * 128) * HH + h * DH;
    #pragma unroll
    for (int mt = 0; mt < 4; mt++) {
        int r0 = wm * 64 + mt * 16 + gid;
        #pragma unroll
        for (int nt = 0; nt < 2; nt++) {
            int col = wn * 16 + nt * 8 + tq2;
            *(float2*)&Cb[(ll)r0 * HH + col] =
                make_float2(a2[mt][nt][0] * inv0[mt], a2[mt][nt][1] * inv0[mt]);
            *(float2*)&Cb[(ll)(r0 + 8) * HH + col] =
                make_float2(a2[mt][nt][2] * inv1[mt], a2[mt][nt][3] * inv1[mt]);
        }
    }
}

// ================= weight packing (transpose + fp16 split) =================
__global__ void pack_w_kernel(const float* __restrict__ W, __half* __restrict__ Ph,
                              __half* __restrict__ Pl, int K, int N)
{
    __shared__ float t[32][33];
    int l = blockIdx.z;
    const float* Wb = W + (ll)l * K * N;
    __half* Phb = Ph + (ll)l * N * K;
    __half* Plb = Pl + (ll)l * N * K;
    int k0 = blockIdx.x * 32, n0 = blockIdx.y * 32;
    int tx = threadIdx.x, ty = threadIdx.y;
    #pragma unroll
    for (int j = 0; j < 4; j++)
        t[ty + j * 8][tx] = Wb[(ll)(k0 + ty + j * 8) * N + n0 + tx];
    __syncthreads();
    #pragma unroll
    for (int j = 0; j < 4; j++) {
        int n = n0 + ty + j * 8, k = k0 + tx;
        float v = t[tx][ty + j * 8];
        __half h = __float2half_rn(v);
        __half lo = __float2half_rn(v - __half2float(h));
        Phb[(ll)n * K + k] = h;
        Plb[(ll)n * K + k] = lo;
    }
}

__global__ void pack_qkvw_kernel(const float* __restrict__ Wq, const float* __restrict__ Wk,
                                 const float* __restrict__ Wv,
                                 __half* __restrict__ Ph, __half* __restrict__ Pl)
{
    __shared__ float t[32][33];
    int l = blockIdx.z;
    int k0 = blockIdx.x * 32, n0 = blockIdx.y * 32;
    int sel = n0 / HH;
    const float* Wb = ((sel == 0) ? Wq : (sel == 1) ? Wk : Wv) + (ll)l * HH * HH;
    int nc0 = n0 - sel * HH;
    __half* Phb = Ph + (ll)l * QKVN * HH;
    __half* Plb = Pl + (ll)l * QKVN * HH;
    int tx = threadIdx.x, ty = threadIdx.y;
    #pragma unroll
    for (int j = 0; j < 4; j++)
        t[ty + j * 8][tx] = Wb[(ll)(k0 + ty + j * 8) * HH + nc0 + tx];
    __syncthreads();
    #pragma unroll
    for (int j = 0; j < 4; j++) {
        int n = n0 + ty + j * 8, k = k0 + tx;
        float v = t[tx][ty + j * 8];
        __half h = __float2half_rn(v);
        __half lo = __float2half_rn(v - __half2float(h));
        Phb[(ll)n * HH + k] = h;
        Plb[(ll)n * HH + k] = lo;
    }
}

__global__ void pack_bias_kernel(const float* __restrict__ bq, const float* __restrict__ bk,
                                 const float* __restrict__ bv, float* __restrict__ bp)
{
    int i = blockIdx.x * 256 + threadIdx.x;
    if (i >= LL * QKVN) return;
    int l = i / QKVN, col = i % QKVN;
    int sel = col / HH, cc = col % HH;
    const float* b = (sel == 0) ? bq : (sel == 1) ? bk : bv;
    bp[i] = b[l * HH + cc];
}

// ---- V transpose + fp16 split: qkv V slice [s][d] -> Vt [bh][d][s] ----
__global__ void vtrans_kernel(const float* __restrict__ qkv,
                              __half* __restrict__ Vh, __half* __restrict__ Vl)
{
    __shared__ float t[32][33];
    int s0 = blockIdx.x * 32;
    int d0 = blockIdx.y * 32;
    int bh = blockIdx.z;
    int b = bh / AH, h = bh % AH;
    const float* src = qkv + (ll)(b * SS) * QKVN + 2 * HH + h * DH;
    int tx = threadIdx.x, ty = threadIdx.y;
    #pragma unroll
    for (int j = 0; j < 4; j++)
        t[ty + j * 8][tx] = src[(ll)(s0 + ty + j * 8) * QKVN + d0 + tx];
    __syncthreads();
    __half* Vhb = Vh + (ll)bh * DH * SS;
    __half* Vlb = Vl + (ll)bh * DH * SS;
    #pragma unroll
    for (int j = 0; j < 4; j++) {
        int d = d0 + ty + j * 8, sidx = s0 + tx;
        float v = t[tx][ty + j * 8];
        __half hh = __float2half_rn(v);
        __half lo = __float2half_rn(v - __half2float(hh));
        Vhb[(ll)d * SS + sidx] = hh;
        Vlb[(ll)d * SS + sidx] = lo;
    }
}

// ================= block reduction =================
template<bool MAXR>
__device__ __forceinline__ float block_reduce(float v) {
    __shared__ float sh[33];
    int lane = threadIdx.x & 31, w = threadIdx.x >> 5;
    #pragma unroll
    for (int o = 16; o; o >>= 1) {
        float t = __shfl_xor_sync(0xffffffffu, v, o);
        v = MAXR ? fmaxf(v, t) : (v + t);
    }
    if (lane == 0) sh[w] = v;
    __syncthreads();
    if (w == 0) {
        int nw = blockDim.x >> 5;
        float t = (lane < nw) ? sh[lane] : (MAXR ? -3.4e38f : 0.f);
        #pragma unroll
        for (int o = 16; o; o >>= 1) {
            float u = __shfl_xor_sync(0xffffffffu, t, o);
            t = MAXR ? fmaxf(t, u) : (t + u);
        }
        if (lane == 0) sh[32] = t;
    }
    __syncthreads();
    float r = sh[32];
    __syncthreads();
    return r;
}

// ================= elementwise kernels =================
__global__ void embed_ln_kernel(const int* __restrict__ ids, const int* __restrict__ types,
                                const float* __restrict__ wemb, const float* __restrict__ pemb,
                                const float* __restrict__ temb,
                                const float* __restrict__ g, const float* __restrict__ b,
                                float* __restrict__ x)
{
    int tok = blockIdx.x;
    int s = tok % SS;
    int t = threadIdx.x;
    int id = ids[tok];
    int ty = types[tok];
    float v[3];
    float sum = 0.f;
    #pragma unroll
    for (int i = 0; i < 3; i++) {
        int h = t + i*256;
        float val = wemb[(ll)id*HH + h] + pemb[s*HH + h] + temb[ty*HH + h];
        v[i] = val; sum += val;
    }
    float mean = block_reduce<false>(sum) * (1.f/HH);
    float sq = 0.f;
    #pragma unroll
    for (int i = 0; i < 3; i++) { float d = v[i] - mean; sq += d*d; }
    float var = block_reduce<false>(sq) * (1.f/HH);
    float rstd = rsqrtf(var + 1e-12f);
    #pragma unroll
    for (int i = 0; i < 3; i++) {
        int h = t + i*256;
        x[(ll)tok*HH + h] = (v[i] - mean) * rstd * g[h] + b[h];
    }
}

__global__ void add_ln_kernel(const float* __restrict__ xin, const float* __restrict__ tmp,
                              const float* __restrict__ g, const float* __restrict__ b,
                              float* __restrict__ xout)
{
    int tok = blockIdx.x;
    int t = threadIdx.x;
    float v[3];
    float sum = 0.f;
    #pragma unroll
    for (int i = 0; i < 3; i++) {
        int h = t + i*256;
        float val = xin[(ll)tok*HH + h] + tmp[(ll)tok*HH + h];
        v[i] = val; sum += val;
    }
    float mean = block_reduce<false>(sum) * (1.f/HH);
    float sq = 0.f;
    #pragma unroll
    for (int i = 0; i < 3; i++) { float d = v[i] - mean; sq += d*d; }
    float var = block_reduce<false>(sq) * (1.f/HH);
    float rstd = rsqrtf(var + 1e-12f);
    #pragma unroll
    for (int i = 0; i < 3; i++) {
        int h = t + i*256;
        xout[(ll)tok*HH + h] = (v[i] - mean) * rstd * g[h] + b[h];
    }
}

__global__ void compact_kernel(const float* __restrict__ x, const int* __restrict__ valid,
                               float* __restrict__ vo)
{
    int b = blockIdx.x;
    int t = threadIdx.x;
    __shared__ int vload[SS];
    __shared__ int rank[SS];
    vload[t] = valid[b*SS + t];
    __syncthreads();
    int r = 0;
    for (int i = 0; i < t; i++) r += vload[i];
    rank[t] = r;
    __syncthreads();
    float* vob = vo + (ll)b * SS * HH;
    for (int i = t; i < SS*HH; i += 256) vob[i] = 0.f;
    __syncthreads();
    int w = t >> 5, lane = t & 31;
    for (int s = w; s < SS; s += 8) {
        if (vload[s]) {
            const float* src = x + ((ll)b*SS + s) * HH;
            float* dst = vob + (ll)rank[s] * HH;
            for (int i = lane; i < HH; i += 32) dst[i] = src[i];
        }
    }
}

__global__ void cls_kernel(const float* __restrict__ vo, const float* __restrict__ W,
                           const float* __restrict__ bias, float* __restrict__ out)
{
    int tok = blockIdx.x;
    int t = threadIdx.x;
    const float* v = vo + (ll)tok * HH;
    float acc[NL];
    #pragma unroll
    for (int j = 0; j < NL; j++) acc[j] = 0.f;
    for (int i = t; i < HH; i += 256) {
        float xv = v[i];
        const float* w = W + (ll)i * NL;
        #pragma unroll
        for (int j = 0; j < NL; j++) acc[j] += xv * w[j];
    }
    __shared__ float red[NL*256];
    #pragma unroll
    for (int j = 0; j < NL; j++) red[j*256 + t] = acc[j];
    __syncthreads();
    for (int o = 128; o; o >>= 1) {
        if (t < o) {
            #pragma unroll
            for (int j = 0; j < NL; j++) red[j*256 + t] += red[j*256 + t + o];
        }
        __syncthreads();
    }
    if (t == 0) {
        float lg[NL];
        float mx = -3.4e38f;
        #pragma unroll
        for (int j = 0; j < NL; j++) { lg[j] = red[j*256] + bias[j]; mx = fmaxf(mx, lg[j]); }
        float s = 0.f;
        #pragma unroll
        for (int j = 0; j < NL; j++) { lg[j] = expf(lg[j] - mx); s += lg[j]; }
        float inv = 1.f / s;
        #pragma unroll
        for (int j = 0; j < NL; j++) out[(ll)tok*NL + j] = lg[j] * inv;
    }
}

// ================= launch orchestration =================
extern "C" void kernel_launch(void* const* d_in, const int* in_sizes, int n_in,
                              void* d_out, int out_size)
{
    const int*   ids   = (const int*)  d_in[0];
    const int*   imask = (const int*)  d_in[1];
    const int*   types = (const int*)  d_in[2];
    const int*   vmask = (const int*)  d_in[3];
    const float* wemb  = (const float*)d_in[4];
    const float* pemb  = (const float*)d_in[5];
    const float* temb  = (const float*)d_in[6];
    const float* eg    = (const float*)d_in[7];
    const float* eb    = (const float*)d_in[8];
    const float* Wq    = (const float*)d_in[9];
    const float* bq    = (const float*)d_in[10];
    const float* Wk    = (const float*)d_in[11];
    const float* bk    = (const float*)d_in[12];
    const float* Wv    = (const float*)d_in[13];
    const float* bv    = (const float*)d_in[14];
    const float* Wo    = (const float*)d_in[15];
    const float* bo    = (const float*)d_in[16];
    const float* ag    = (const float*)d_in[17];
    const float* ab    = (const float*)d_in[18];
    const float* W1    = (const float*)d_in[19];
    const float* b1    = (const float*)d_in[20];
    const float* W2    = (const float*)d_in[21];
    const float* b2    = (const float*)d_in[22];
    const float* fg    = (const float*)d_in[23];
    const float* fb    = (const float*)d_in[24];
    const float* cW    = (const float*)d_in[25];
    const float* cb    = (const float*)d_in[26];
    float* out = (float*)d_out;

    float *x, *qkv, *ctx, *tmp, *hbuf, *vo, *bqkv;
    __half *qkvw_h, *qkvw_l, *ow_h, *ow_l, *f1w_h, *f1w_l, *f2w_h, *f2w_l, *vt_h, *vt_l;
    cudaGetSymbolAddress((void**)&x,    g_x);
    cudaGetSymbolAddress((void**)&qkv,  g_qkv);
    cudaGetSymbolAddress((void**)&ctx,  g_ctx);
    cudaGetSymbolAddress((void**)&tmp,  g_tmp);
    cudaGetSymbolAddress((void**)&hbuf, g_h);
    cudaGetSymbolAddress((void**)&vo,   g_vo);
    cudaGetSymbolAddress((void**)&bqkv, g_bqkv);
    cudaGetSymbolAddress((void**)&qkvw_h, g_qkvw_h);
    cudaGetSymbolAddress((void**)&qkvw_l, g_qkvw_l);
    cudaGetSymbolAddress((void**)&ow_h,   g_ow_h);
    cudaGetSymbolAddress((void**)&ow_l,   g_ow_l);
    cudaGetSymbolAddress((void**)&f1w_h,  g_f1w_h);
    cudaGetSymbolAddress((void**)&f1w_l,  g_f1w_l);
    cudaGetSymbolAddress((void**)&f2w_h,  g_f2w_h);
    cudaGetSymbolAddress((void**)&f2w_l,  g_f2w_l);
    cudaGetSymbolAddress((void**)&vt_h,   g_vt_h);
    cudaGetSymbolAddress((void**)&vt_l,   g_vt_l);

    cudaFuncSetAttribute(hgemm<1,0>, cudaFuncAttributeMaxDynamicSharedMemorySize, HG_SMEM);
    cudaFuncSetAttribute(hgemm<1,1>, cudaFuncAttributeMaxDynamicSharedMemorySize, HG_SMEM);
    cudaFuncSetAttribute(fattn_kernel, cudaFuncAttributeMaxDynamicSharedMemorySize, AT_SMEM);

    // 0) pack weights: transpose to [N][K], split fp16 hi/lo
    {
        dim3 blk(32, 8);
        pack_qkvw_kernel<<<dim3(HH/32, QKVN/32, LL), blk>>>(Wq, Wk, Wv, qkvw_h, qkvw_l);
        pack_w_kernel<<<dim3(HH/32, HH/32, LL),  blk>>>(Wo, ow_h,  ow_l,  HH, HH);
        pack_w_kernel<<<dim3(HH/32, FF/32, LL),  blk>>>(W1, f1w_h, f1w_l, HH, FF);
        pack_w_kernel<<<dim3(FF/32, HH/32, LL),  blk>>>(W2, f2w_h, f2w_l, FF, HH);
        pack_bias_kernel<<<(LL*QKVN + 255)/256, 256>>>(bq, bk, bv, bqkv);
    }

    // 1) embeddings + LN
    embed_ln_kernel<<<NT, 256>>>(ids, types, wemb, pemb, temb, eg, eb, x);

    // 2) transformer layers
    for (int l = 0; l < LL; l++) {
        const float* bol = bo + (ll)l*HH;
        const float* b1l = b1 + (ll)l*FF;
        const float* b2l = b2 + (ll)l*HH;
        const float* agl = ag + (ll)l*HH;    const float* abl = ab + (ll)l*HH;
        const float* fgl = fg + (ll)l*HH;    const float* fbl = fb + (ll)l*HH;

        // fused QKV projection
        hgemm_launch<1,0>(x, nullptr, qkvw_h + (ll)l*QKVN*HH, qkvw_l + (ll)l*QKVN*HH,
                          bqkv + (ll)l*QKVN, qkv, NT, QKVN, HH, HH, HH, QKVN, 1,
                          1,0,0, 1,0,0, 1,0,0);

        // V transpose + split
        vtrans_kernel<<<dim3(SS/32, DH/32, NBH), dim3(32, 8)>>>(qkv, vt_h, vt_l);

        // fused attention: QK^T + softmax + P*V
        fattn_kernel<<<dim3(2, NBH), 256, AT_SMEM>>>(qkv, vt_h, vt_l, imask, ctx);

        // output projection
        hgemm_launch<1,0>(ctx, nullptr, ow_h + (ll)l*HH*HH, ow_l + (ll)l*HH*HH,
                          bol, tmp, NT, HH, HH, HH, HH, HH, 1,
                          1,0,0, 1,0,0, 1,0,0);
        add_ln_kernel<<<NT, 256>>>(x, tmp, agl, abl, x);

        // FFN
        hgemm_launch<1,1>(x, nullptr, f1w_h + (ll)l*FF*HH, f1w_l + (ll)l*FF*HH,
                          b1l, hbuf, NT, FF, HH, HH, HH, FF, 1,
                          1,0,0, 1,0,0, 1,0,0);
        hgemm_launch<1,0>(hbuf, nullptr, f2w_h + (ll)l*HH*FF, f2w_l + (ll)l*HH*FF,
                          b2l, tmp, NT, HH, FF, FF, FF, HH, 1,
                          1,0,0, 1,0,0, 1,0,0);
        add_ln_kernel<<<NT, 256>>>(x, tmp, fgl, fbl, x);
    }

    // 3) valid-token compaction
    compact_kernel<<<BB, 256>>>(x, vmask, vo);

    // 4) classifier + softmax
    cls_kernel<<<NT, 256>>>(vo, cW, cb, out);

    (void)in_sizes; (void)n_in; (void)out_size;
}